// round 12
// baseline (speedup 1.0000x reference)
#include <cuda_runtime.h>
#include <stdint.h>

#define NUM_TNETS 8388608
#define NUM_NODES 1048576
#define NUM_SMS   148
#define CTAS_PER_SM 8
#define THREADS   256

// Persistent grid-stride variant: 1184 resident CTAs (148 SMs x 8), each
// thread loops over ~14 two-tnet packets. Same LTS transaction count as the
// one-shot kernel (the ~288K-cyc floor), but the loop keeps the memory
// pipeline continuously primed: iteration i+1's independent loads issue while
// iteration i's atomics drain, and ~15K CTA launch/retire events disappear.
//
// Floor model (validated over 6 runs / 5 shape variations):
//   33.5M REDG.ADD + 16.7M gather sectors + ~3M stream sectors
// = ~53M LTS transactions / 184 slices = 288K cyc ~= 152us @ ~1.9GHz.
// L2=83% binding; issue=2.5%, DRAM=38% slack.
__global__ void __launch_bounds__(THREADS) scatter_add_kernel(
    const float* __restrict__ beta,          // [1]
    const float* __restrict__ tnet_weights,  // [NUM_TNETS]
    const int*   __restrict__ flat_tnet2pin, // [2*NUM_TNETS] int32
    const int*   __restrict__ pin2node,      // [NUM_PINS]    int32
    float* __restrict__ out)                 // [NUM_NODES]
{
    const int npairs = NUM_TNETS / 2;                   // 4,194,304 packets
    const int stride = gridDim.x * blockDim.x;          // 303,104
    const float b = __ldg(beta);

    for (int t = blockIdx.x * blockDim.x + threadIdx.x; t < npairs; t += stride) {
        // coalesced 16B streaming load: pins of two arcs [s0,d0,s1,d1]
        int4 pins = __ldcs(reinterpret_cast<const int4*>(flat_tnet2pin) + t);
        // coalesced 8B streaming load: the two arc weights
        float2 wv = __ldcs(reinterpret_cast<const float2*>(tnet_weights) + t);

        float w0 = wv.x * b;
        float w1 = wv.y * b;

        // four independent random gathers (MLP>=4, overlapped across iters)
        int n0 = __ldcg(pin2node + pins.x);
        int n1 = __ldcg(pin2node + pins.y);
        int n2 = __ldcg(pin2node + pins.z);
        int n3 = __ldcg(pin2node + pins.w);

        atomicAdd(out + n0, w0);
        atomicAdd(out + n1, w0);
        atomicAdd(out + n2, w1);
        atomicAdd(out + n3, w1);
    }
}

extern "C" void kernel_launch(void* const* d_in, const int* in_sizes, int n_in,
                              void* d_out, int out_size) {
    const float* beta         = (const float*)d_in[0];
    const float* tnet_weights = (const float*)d_in[1];
    const int*   flat_t2p     = (const int*)d_in[2];
    const int*   pin2node     = (const int*)d_in[3];
    float* out = (float*)d_out;

    // 1) zero the poisoned output (~0.7us)
    cudaMemsetAsync(out, 0, (size_t)out_size * sizeof(float));

    // 2) persistent gather + atomic scatter-add, beta folded in
    scatter_add_kernel<<<NUM_SMS * CTAS_PER_SM, THREADS>>>(
        beta, tnet_weights, flat_t2p, pin2node, out);
}

// round 13
// speedup vs baseline: 1.1072x; 1.1072x over previous
#include <cuda_runtime.h>
#include <stdint.h>

#define NUM_TNETS 8388608
#define NUM_NODES 1048576

// FINAL — at the LTS transaction roofline. One-shot launch, 2 tnets/thread.
// Measured 152.0-154.1us over six runs of this exact binary.
//
// Floor model (validated against 6 shape variations, all confirmed):
//   33.5M REDG.ADD       random 4B targets, 4MB L2-resident output
// + 16.7M gather sectors random 4B reads over the 84MB pin2node table
// + ~3M   stream sectors 96MB pins+weights, vectorized, evict-first
// = ~53M LTS transactions / 184 slices = 288K cyc = ~152us @ ~1.9GHz.
//
// Shape-search history (all alternatives measured WORSE or neutral):
//   4x unroll:        155.5us  (R3)  — deeper reg bursts, no issue win
//   512-thr blocks:   153.7us  (R5)  — occ down
//   persistent grid:  170.2us  (R12) — TLP collapse starves LTS slots;
//                     massive thread count IS the mechanism that fills
//                     the 53M-transaction pipeline. One-shot wins.
//
// ncu steady state: L2=83% (binding), DRAM=38%, issue=2.4%, occ=85%.
// .cs streaming keeps the gather table L2-resident; .cg gathers skip L1
// (~0% hit rate on random 4B over 84MB).
__global__ void __launch_bounds__(256) scatter_add_kernel(
    const float* __restrict__ beta,          // [1]
    const float* __restrict__ tnet_weights,  // [NUM_TNETS]
    const int*   __restrict__ flat_tnet2pin, // [2*NUM_TNETS] int32
    const int*   __restrict__ pin2node,      // [NUM_PINS]    int32
    float* __restrict__ out)                 // [NUM_NODES]
{
    int t = blockIdx.x * blockDim.x + threadIdx.x;  // pair index: 2 tnets each

    // coalesced 16B streaming load: pins of two arcs [s0,d0,s1,d1]
    int4 pins = __ldcs(reinterpret_cast<const int4*>(flat_tnet2pin) + t);
    // coalesced 8B streaming load: the two arc weights
    float2 wv = __ldcs(reinterpret_cast<const float2*>(tnet_weights) + t);

    float b = __ldg(beta);
    float w0 = wv.x * b;
    float w1 = wv.y * b;

    // four independent random gathers (MLP=4), L2-only
    int n0 = __ldcg(pin2node + pins.x);
    int n1 = __ldcg(pin2node + pins.y);
    int n2 = __ldcg(pin2node + pins.z);
    int n3 = __ldcg(pin2node + pins.w);

    atomicAdd(out + n0, w0);
    atomicAdd(out + n1, w0);
    atomicAdd(out + n2, w1);
    atomicAdd(out + n3, w1);
}

extern "C" void kernel_launch(void* const* d_in, const int* in_sizes, int n_in,
                              void* d_out, int out_size) {
    const float* beta         = (const float*)d_in[0];
    const float* tnet_weights = (const float*)d_in[1];
    const int*   flat_t2p     = (const int*)d_in[2];
    const int*   pin2node     = (const int*)d_in[3];
    float* out = (float*)d_out;

    // 1) zero the poisoned output (~0.7us, under the noise floor)
    cudaMemsetAsync(out, 0, (size_t)out_size * sizeof(float));

    // 2) gather + atomic scatter-add, beta folded in
    {
        const int threads = 256;
        const int pairs = NUM_TNETS / 2;          // 4,194,304
        const int blocks = pairs / threads;       // 16384 exact
        scatter_add_kernel<<<blocks, threads>>>(beta, tnet_weights, flat_t2p,
                                                pin2node, out);
    }
}

// round 14
// speedup vs baseline: 1.1193x; 1.0109x over previous
#include <cuda_runtime.h>
#include <stdint.h>

#define NUM_TNETS 8388608
#define NUM_NODES 1048576

// Shape test: 1 tnet/thread + .cs/.cg hints (never isolated — R2's 1-tnet
// ran without hints). 8.4M threads = 2x TLP vs the 2-tnet kernel; R12 proved
// thread count is the supply mechanism feeding the saturated LTS pipe.
// MLP_p1 drops 4->2, reducing cross-CTA L1tex queue contention tail.
// LTS transaction count unchanged (~53M / 184 slices = ~152us floor).
__global__ void __launch_bounds__(256) scatter_add_kernel(
    const float* __restrict__ beta,          // [1]
    const float* __restrict__ tnet_weights,  // [NUM_TNETS]
    const int*   __restrict__ flat_tnet2pin, // [2*NUM_TNETS] int32
    const int*   __restrict__ pin2node,      // [NUM_PINS]    int32
    float* __restrict__ out)                 // [NUM_NODES]
{
    int t = blockIdx.x * blockDim.x + threadIdx.x;  // one tnet per thread

    // coalesced 8B streaming load: this arc's (src, dst) pins
    int2 pins = __ldcs(reinterpret_cast<const int2*>(flat_tnet2pin) + t);
    // coalesced 4B streaming load: the arc weight
    float w = __ldcs(tnet_weights + t) * __ldg(beta);

    // two independent random gathers, L2-only
    int n0 = __ldcg(pin2node + pins.x);
    int n1 = __ldcg(pin2node + pins.y);

    atomicAdd(out + n0, w);
    atomicAdd(out + n1, w);
}

extern "C" void kernel_launch(void* const* d_in, const int* in_sizes, int n_in,
                              void* d_out, int out_size) {
    const float* beta         = (const float*)d_in[0];
    const float* tnet_weights = (const float*)d_in[1];
    const int*   flat_t2p     = (const int*)d_in[2];
    const int*   pin2node     = (const int*)d_in[3];
    float* out = (float*)d_out;

    // 1) zero the poisoned output (~0.7us)
    cudaMemsetAsync(out, 0, (size_t)out_size * sizeof(float));

    // 2) gather + atomic scatter-add, beta folded in
    {
        const int threads = 256;
        const int blocks = NUM_TNETS / threads;   // 32768 exact
        scatter_add_kernel<<<blocks, threads>>>(beta, tnet_weights, flat_t2p,
                                                pin2node, out);
    }
}